// round 6
// baseline (speedup 1.0000x reference)
#include <cuda_runtime.h>
#include <cuda_fp16.h>
#include <cstdint>

#define LATENT   128
#define HIDDEN   2048
#define NPARTS   128
#define KCOLS    2048
#define OMEGA_D  1152
#define TRANZ_D  384
#define TRANSF_D 1536

// ---------------------------------------------------------------------------
// Scratch (__device__ globals; allocation-guard-safe)
// ---------------------------------------------------------------------------
#define W_TOTAL (2048*128 + 2048*2048 + 2048*2048 + 1152*2048 + \
                 2048*128 + 2048*2048 + 2048*2048 + 384*2048)

__device__ __half g_w_hi[W_TOTAL];
__device__ __half g_w_lo[W_TOTAL];
__device__ __half g_act_hi[2][HIDDEN * KCOLS];
__device__ __half g_act_lo[2][HIDDEN * KCOLS];
__device__ __half g_xt_hi[KCOLS * LATENT];
__device__ __half g_xt_lo[KCOLS * LATENT];
__device__ float g_omega_t[(size_t)KCOLS * OMEGA_D];
__device__ float g_trans_part[3 * (size_t)KCOLS * TRANZ_D];

// ---------------------------------------------------------------------------
// PTX helpers (base ISA: ldmatrix / mma.sync / cp.async)
// ---------------------------------------------------------------------------
__device__ __forceinline__ uint32_t smem_u32(const void* p) {
    uint32_t a;
    asm("{ .reg .u64 t; cvta.to.shared.u64 t, %1; cvt.u32.u64 %0, t; }" : "=r"(a) : "l"(p));
    return a;
}
__device__ __forceinline__ void cp16(uint32_t s, const void* g) {
    asm volatile("cp.async.cg.shared.global [%0], [%1], 16;" :: "r"(s), "l"(g) : "memory");
}
#define CP_COMMIT() asm volatile("cp.async.commit_group;" ::: "memory")

__device__ __forceinline__ void ldsm_x4(uint32_t addr, uint32_t* r) {
    asm volatile("ldmatrix.sync.aligned.m8n8.x4.shared.b16 {%0,%1,%2,%3}, [%4];"
                 : "=r"(r[0]), "=r"(r[1]), "=r"(r[2]), "=r"(r[3]) : "r"(addr));
}
__device__ __forceinline__ void mma_f16(float* c, const uint32_t* a,
                                        uint32_t b0, uint32_t b1) {
    asm volatile(
        "mma.sync.aligned.m16n8k16.row.col.f32.f16.f16.f32 "
        "{%0,%1,%2,%3}, {%4,%5,%6,%7}, {%8,%9}, {%0,%1,%2,%3};"
        : "+f"(c[0]), "+f"(c[1]), "+f"(c[2]), "+f"(c[3])
        : "r"(a[0]), "r"(a[1]), "r"(a[2]), "r"(a[3]), "r"(b0), "r"(b1));
}

// ---------------------------------------------------------------------------
// Fused weight split: all 8 weights -> (hi, lo) fp16, one launch.
// ---------------------------------------------------------------------------
__global__ __launch_bounds__(256) void split_w_kernel(
    const float* __restrict__ w0, const float* __restrict__ w1,
    const float* __restrict__ w2, const float* __restrict__ w3,
    const float* __restrict__ w4, const float* __restrict__ w5,
    const float* __restrict__ w6, const float* __restrict__ w7,
    __half* __restrict__ hi, __half* __restrict__ lo)
{
    const int cum[8] = {65536, 1114112, 2162688, 2752512,
                        2818048, 3866624, 4915200, 5111808};
    int idx = blockIdx.x * 256 + threadIdx.x;
    if (idx >= 5111808) return;
    const float* srcs[8] = {w0, w1, w2, w3, w4, w5, w6, w7};
    int s = 0;
#pragma unroll
    for (int i = 0; i < 7; i++) s += (idx >= cum[i]);
    int local = idx - (s ? cum[s - 1] : 0);
    float4 v = ((const float4*)srcs[s])[local];
    float f[4] = {v.x, v.y, v.z, v.w};
    __align__(8) __half h[4], l[4];
#pragma unroll
    for (int j = 0; j < 4; j++) {
        h[j] = __float2half(f[j]);
        l[j] = __float2half(f[j] - __half2float(h[j]));
    }
    ((uint2*)hi)[idx] = *(const uint2*)h;
    ((uint2*)lo)[idx] = *(const uint2*)l;
}

__global__ __launch_bounds__(256) void split_xT_kernel(
    const float* __restrict__ x, __half* __restrict__ hi,
    __half* __restrict__ lo)
{
    int i = blockIdx.x * 256 + threadIdx.x;  // i = n*LATENT + f
    int f = i & (LATENT - 1);
    int n = i >> 7;
    float v = x[(size_t)f * KCOLS + n];
    __half h = __float2half(v);
    hi[i] = h;
    lo[i] = __float2half(v - __half2float(h));
}

// ---------------------------------------------------------------------------
// HMMA split-fp16 GEMM (3-MMA scheme).
//   C[M, KCOLS] = A[M, Kd] @ Bt[KCOLS, Kd]^T, output TRANSPOSED [n][M].
// CTA tile 128x256x32, 256 threads (8 warps), warp tile 64x64 (2m x 4n),
// 3-stage cp.async pipeline, single barrier per K-step, single wave (128 CTAs).
// ---------------------------------------------------------------------------
#define BM 128
#define BN 256
#define BK 32
#define GT 256
#define PITCH 80
#define T_A (128 * PITCH)            // 10240 per A half
#define T_B (256 * PITCH)            // 20480 per B half
#define OFF_AH 0
#define OFF_AL T_A
#define OFF_BH (2 * T_A)
#define OFF_BL (2 * T_A + T_B)
#define STAGE_B (2 * T_A + 2 * T_B)  // 61440
#define NSTAGE 3
#define GEMM_SMEM (NSTAGE * STAGE_B) // 184320

__device__ __forceinline__ void load_stage(
    const __half* __restrict__ Ah, const __half* __restrict__ Al,
    const __half* __restrict__ Bh, const __half* __restrict__ Bl,
    int Kd, int m0, int n0, int kk, uint32_t stage_sb, int tid)
{
    // 768 rows total (Ah 128, Al 128, Bh 256, Bl 256), 4x16B chunks each.
#pragma unroll
    for (int i = 0; i < 12; i++) {
        const int c = tid + i * 256;        // 0..3071
        const int row = c >> 2;
        const int cb = (c & 3) * 16;
        const __half* gsrc;
        int grow;
        uint32_t soff;
        if (row < 128)      { gsrc = Ah; grow = m0 + row;       soff = OFF_AH + row * PITCH; }
        else if (row < 256) { gsrc = Al; grow = m0 + row - 128; soff = OFF_AL + (row - 128) * PITCH; }
        else if (row < 512) { gsrc = Bh; grow = n0 + row - 256; soff = OFF_BH + (row - 256) * PITCH; }
        else                { gsrc = Bl; grow = n0 + row - 512; soff = OFF_BL + (row - 512) * PITCH; }
        cp16(stage_sb + soff + cb,
             (const char*)(gsrc + (size_t)grow * Kd + kk) + cb);
    }
}

__global__ __launch_bounds__(GT, 1) void gemm_hmma_kernel(
    const __half* __restrict__ A_hi, const __half* __restrict__ A_lo,
    const __half* __restrict__ B_hi, const __half* __restrict__ B_lo,
    __half* __restrict__ out_hi, __half* __restrict__ out_lo,
    float* __restrict__ out_f32, int M, int Kd, int mode,
    int ktps, size_t out_stride)
{
    extern __shared__ __align__(128) char smem[];
    const uint32_t sb = smem_u32(smem);
    const int tid = threadIdx.x;
    const int lane = tid & 31;
    const int wid = tid >> 5;                 // 0..7
    const int warp_m0 = (wid & 1) * 64;       // 2 m-warps
    const int warp_n0 = (wid >> 1) * 64;      // 4 n-warps (64 n each)
    const int m0 = blockIdx.y * BM;
    const int n0 = blockIdx.x * BN;
    const int KT = Kd / BK;
    const int ktb = blockIdx.z * ktps;
    const int L = min(KT - ktb, ktps);
    out_f32 += (size_t)blockIdx.z * out_stride;

    const int a_row = (lane & 7) + ((lane >> 3) & 1) * 8;
    const int a_kb  = (lane >> 4) * 16;
    const int b_row = (lane & 7) + (lane >> 4) * 8;
    const int b_kb  = ((lane >> 3) & 1) * 16;

    float acc[2][8][4];   // mt x nt x 4   (64x64 warp tile)
#pragma unroll
    for (int mt = 0; mt < 2; mt++)
#pragma unroll
        for (int nt = 0; nt < 8; nt++)
#pragma unroll
            for (int i = 0; i < 4; i++) acc[mt][nt][i] = 0.0f;
    // NOTE: warp tile is 64 m x 64 n -> mt in 0..3? 64/16 = 4 m-tiles.
    // Use acc2 layout: [4][8][4] is 128 regs; declare properly below.

    float acc2[4][8][4];
#pragma unroll
    for (int mt = 0; mt < 4; mt++)
#pragma unroll
        for (int nt = 0; nt < 8; nt++)
#pragma unroll
            for (int i = 0; i < 4; i++) acc2[mt][nt][i] = 0.0f;
    (void)acc;

    load_stage(A_hi, A_lo, B_hi, B_lo, Kd, m0, n0, ktb * BK, sb, tid);
    CP_COMMIT();
    load_stage(A_hi, A_lo, B_hi, B_lo, Kd, m0, n0, (ktb + 1) * BK, sb + STAGE_B, tid);
    CP_COMMIT();

    for (int kt = 0; kt < L; kt++) {
        asm volatile("cp.async.wait_group 1;" ::: "memory");
        __syncthreads();

        if (kt + 2 < L) {
            load_stage(A_hi, A_lo, B_hi, B_lo, Kd, m0, n0, (ktb + kt + 2) * BK,
                       sb + ((kt + 2) % NSTAGE) * STAGE_B, tid);
        }
        CP_COMMIT();

        const uint32_t st = sb + (kt % NSTAGE) * STAGE_B;
#pragma unroll
        for (int ks = 0; ks < 2; ks++) {
            const int kb = ks * 32;
            uint32_t bh[4][4], bl[4][4];
#pragma unroll
            for (int g = 0; g < 4; g++) {
                uint32_t rb = st + (warp_n0 + g * 16 + b_row) * PITCH + kb + b_kb;
                ldsm_x4(rb + OFF_BH, bh[g]);
                ldsm_x4(rb + OFF_BL, bl[g]);
            }
#pragma unroll
            for (int mt = 0; mt < 4; mt++) {
                uint32_t ah[4], al[4];
                uint32_t ra = st + (warp_m0 + mt * 16 + a_row) * PITCH + kb + a_kb;
                ldsm_x4(ra + OFF_AH, ah);
                ldsm_x4(ra + OFF_AL, al);
#pragma unroll
                for (int nt = 0; nt < 8; nt++) {
                    const int g = nt >> 1, p = (nt & 1) * 2;
                    mma_f16(acc2[mt][nt], ah, bh[g][p], bh[g][p + 1]);
                    mma_f16(acc2[mt][nt], ah, bl[g][p], bl[g][p + 1]);
                    mma_f16(acc2[mt][nt], al, bh[g][p], bh[g][p + 1]);
                }
            }
        }
    }

    // ---------------- epilogue: transpose via SMEM (256 x 132 fp32) --------
    __syncthreads();
    float* sC = (float*)smem;
    const int crow = lane >> 2, ccol = (lane & 3) * 2;
#pragma unroll
    for (int mt = 0; mt < 4; mt++)
#pragma unroll
        for (int nt = 0; nt < 8; nt++) {
            const int m_ = warp_m0 + mt * 16 + crow;
            const int n_ = warp_n0 + nt * 8 + ccol;
            const float* c = acc2[mt][nt];
            sC[(size_t)n_ * 132 + m_]           = c[0];
            sC[(size_t)(n_ + 1) * 132 + m_]     = c[1];
            sC[(size_t)n_ * 132 + m_ + 8]       = c[2];
            sC[(size_t)(n_ + 1) * 132 + m_ + 8] = c[3];
        }
    __syncthreads();

    const int r = tid;                 // n row 0..255
    const size_t base = (size_t)(n0 + r) * M + m0;
    const float* srow = &sC[(size_t)r * 132];
    if (mode == 0) {
#pragma unroll
        for (int j0 = 0; j0 < 128; j0 += 8) {
            __align__(16) __half h8[8], l8[8];
#pragma unroll
            for (int j = 0; j < 8; j++) {
                float v = fmaxf(srow[j0 + j], 0.0f);
                __half h = __float2half(v);
                h8[j] = h;
                l8[j] = __float2half(v - __half2float(h));
            }
            *(uint4*)(out_hi + base + j0) = *(const uint4*)h8;
            *(uint4*)(out_lo + base + j0) = *(const uint4*)l8;
        }
    } else {
#pragma unroll
        for (int j0 = 0; j0 < 128; j0 += 4) {
            float4 v;
            v.x = srow[j0 + 0]; v.y = srow[j0 + 1];
            v.z = srow[j0 + 2]; v.w = srow[j0 + 3];
            *(float4*)(out_f32 + base + j0) = v;
        }
    }
}

// ---------------------------------------------------------------------------
// expm (3x3) + output assembly; sums 3 split-K partials for translations.
// ---------------------------------------------------------------------------
__device__ __forceinline__ void mm3(const float* X, const float* Y, float* Z) {
#pragma unroll
    for (int r = 0; r < 3; r++)
#pragma unroll
        for (int c = 0; c < 3; c++)
            Z[3 * r + c] = fmaf(X[3 * r + 0], Y[c],
                           fmaf(X[3 * r + 1], Y[3 + c], X[3 * r + 2] * Y[6 + c]));
}

__device__ void expm3(const float* A, float* E) {
    float n0 = fabsf(A[0]) + fabsf(A[1]) + fabsf(A[2]);
    float n1 = fabsf(A[3]) + fabsf(A[4]) + fabsf(A[5]);
    float n2 = fabsf(A[6]) + fabsf(A[7]) + fabsf(A[8]);
    float nrm = fmaxf(n0, fmaxf(n1, n2));
    int s = 0;
    if (nrm > 0.25f) {
        s = (int)ceilf(log2f(nrm * 4.0f));
        if (s < 0) s = 0;
    }
    float sc = exp2f((float)(-s));
    float B[9], T[9];
#pragma unroll
    for (int i = 0; i < 9; i++) B[i] = A[i] * sc;
#pragma unroll
    for (int i = 0; i < 9; i++) {
        T[i] = B[i];
        E[i] = ((i == 0) | (i == 4) | (i == 8)) ? 1.0f + B[i] : B[i];
    }
#pragma unroll
    for (int j = 2; j <= 10; j++) {
        float Tn[9];
        mm3(T, B, Tn);
        float inv = 1.0f / (float)j;
#pragma unroll
        for (int i = 0; i < 9; i++) { Tn[i] *= inv; E[i] += Tn[i]; T[i] = Tn[i]; }
    }
    for (int q = 0; q < s; q++) {
        float S[9];
        mm3(E, E, S);
#pragma unroll
        for (int i = 0; i < 9; i++) E[i] = S[i];
    }
}

__global__ __launch_bounds__(256) void expm_assemble_kernel(
    const float* __restrict__ omega_t,    // (K, 9n)
    const float* __restrict__ trans_part, // 3 x (K, 3n)
    float* __restrict__ omega_out,        // (9n, K)
    float* __restrict__ transf,           // (12n, K)
    float* __restrict__ rot,              // (9n, K)
    float* __restrict__ trans_out)        // (3n, K)
{
    const int n = blockIdx.x * 256 + threadIdx.x;
    const int p = blockIdx.y;
    const size_t S = (size_t)KCOLS * TRANZ_D;

    float Am[9];
    const float* src = omega_t + (size_t)n * OMEGA_D + 9 * p;
#pragma unroll
    for (int j = 0; j < 9; j++) Am[j] = __ldg(src + j);

    float E[9];
    expm3(Am, E);

#pragma unroll
    for (int j = 0; j < 9; j++) {
        omega_out[(size_t)(9 * p + j) * KCOLS + n] = Am[j];
        rot[(size_t)(9 * p + j) * KCOLS + n]       = E[j];
        transf[(size_t)(12 * p + j) * KCOLS + n]   = E[j];
    }
    const size_t tbase = (size_t)n * TRANZ_D + 3 * p;
#pragma unroll
    for (int c = 0; c < 3; c++) {
        float tv = __ldg(trans_part + tbase + c)
                 + __ldg(trans_part + S + tbase + c)
                 + __ldg(trans_part + 2 * S + tbase + c);
        trans_out[(size_t)(3 * p + c) * KCOLS + n]   = tv;
        transf[(size_t)(12 * p + 9 + c) * KCOLS + n] = tv;
    }
}

// ---------------------------------------------------------------------------
// kernel_launch
// ---------------------------------------------------------------------------
extern "C" void kernel_launch(void* const* d_in, const int* in_sizes, int n_in,
                              void* d_out, int out_size)
{
    const float* x = (const float*)d_in[0];
    const float* W[8];
    for (int i = 0; i < 8; i++) W[i] = (const float*)d_in[1 + i];

    const int wsz[8] = {2048 * 128, 2048 * 2048, 2048 * 2048, 1152 * 2048,
                        2048 * 128, 2048 * 2048, 2048 * 2048, 384 * 2048};
    size_t woff[8];
    size_t acc = 0;
    for (int i = 0; i < 8; i++) { woff[i] = acc; acc += wsz[i]; }

    float* out    = (float*)d_out;
    float* omega  = out;
    float* transf = omega  + (size_t)OMEGA_D  * KCOLS;
    float* rot    = transf + (size_t)TRANSF_D * KCOLS;
    float* trans  = rot    + (size_t)OMEGA_D  * KCOLS;

    __half *w_hi, *w_lo, *xt_hi, *xt_lo;
    __half *a_hi[2], *a_lo[2];
    float *omega_t, *trans_part;
    cudaGetSymbolAddress((void**)&w_hi, g_w_hi);
    cudaGetSymbolAddress((void**)&w_lo, g_w_lo);
    cudaGetSymbolAddress((void**)&xt_hi, g_xt_hi);
    cudaGetSymbolAddress((void**)&xt_lo, g_xt_lo);
    {
        __half* p;
        cudaGetSymbolAddress((void**)&p, g_act_hi);
        a_hi[0] = p; a_hi[1] = p + (size_t)HIDDEN * KCOLS;
        cudaGetSymbolAddress((void**)&p, g_act_lo);
        a_lo[0] = p; a_lo[1] = p + (size_t)HIDDEN * KCOLS;
    }
    cudaGetSymbolAddress((void**)&omega_t, g_omega_t);
    cudaGetSymbolAddress((void**)&trans_part, g_trans_part);

    cudaFuncSetAttribute(gemm_hmma_kernel,
                         cudaFuncAttributeMaxDynamicSharedMemorySize, GEMM_SMEM);

    // 1) fused weight split + xT split
    split_w_kernel<<<(5111808 + 255) / 256, 256>>>(
        W[0], W[1], W[2], W[3], W[4], W[5], W[6], W[7], w_hi, w_lo);
    split_xT_kernel<<<(KCOLS * LATENT) / 256, 256>>>(x, xt_hi, xt_lo);

    // 2) GEMM chains
    auto gemm = [&](int wi, const __half* bh, const __half* bl,
                    __half* oh, __half* ol, float* of,
                    int M, int Kd, int mode, int zsplits, size_t ostride) {
        int KT = Kd / BK;
        int ktps = (KT + zsplits - 1) / zsplits;
        dim3 grid(KCOLS / BN, M / BM, zsplits);
        gemm_hmma_kernel<<<grid, GT, GEMM_SMEM>>>(
            w_hi + woff[wi], w_lo + woff[wi], bh, bl, oh, ol, of,
            M, Kd, mode, ktps, ostride);
    };

    // omega branch
    gemm(0, xt_hi,   xt_lo,   a_hi[0], a_lo[0], nullptr, HIDDEN,  LATENT, 0, 1, 0);
    gemm(1, a_hi[0], a_lo[0], a_hi[1], a_lo[1], nullptr, HIDDEN,  HIDDEN, 0, 1, 0);
    gemm(2, a_hi[1], a_lo[1], a_hi[0], a_lo[0], nullptr, HIDDEN,  HIDDEN, 0, 1, 0);
    gemm(3, a_hi[0], a_lo[0], nullptr, nullptr, omega_t, OMEGA_D, HIDDEN, 1, 1, 0);
    // translation branch; final layer split-K x3
    gemm(4, xt_hi,   xt_lo,   a_hi[0], a_lo[0], nullptr, HIDDEN,  LATENT, 0, 1, 0);
    gemm(5, a_hi[0], a_lo[0], a_hi[1], a_lo[1], nullptr, HIDDEN,  HIDDEN, 0, 1, 0);
    gemm(6, a_hi[1], a_lo[1], a_hi[0], a_lo[0], nullptr, HIDDEN,  HIDDEN, 0, 1, 0);
    gemm(7, a_hi[0], a_lo[0], nullptr, nullptr, trans_part, TRANZ_D, HIDDEN, 1,
         3, (size_t)KCOLS * TRANZ_D);

    // 3) expm + assembly
    dim3 ge(KCOLS / 256, NPARTS);
    expm_assemble_kernel<<<ge, 256>>>(omega_t, trans_part, omega, transf, rot, trans);
}

// round 7
// speedup vs baseline: 1.5186x; 1.5186x over previous
#include <cuda_runtime.h>
#include <cuda_fp16.h>
#include <cstdint>

#define LATENT   128
#define HIDDEN   2048
#define NPARTS   128
#define KCOLS    2048
#define OMEGA_D  1152
#define TRANZ_D  384
#define TRANSF_D 1536

// ---------------------------------------------------------------------------
// Scratch (__device__ globals; allocation-guard-safe)
// ---------------------------------------------------------------------------
#define W_TOTAL (2048*128 + 2048*2048 + 2048*2048 + 1152*2048 + \
                 2048*128 + 2048*2048 + 2048*2048 + 384*2048)

__device__ __half g_w_hi[W_TOTAL];
__device__ __half g_w_lo[W_TOTAL];
__device__ __half g_act[2][HIDDEN * KCOLS];     // plain fp16 activations
__device__ __half g_xt[KCOLS * LATENT];
__device__ float g_omega_part[2 * (size_t)KCOLS * OMEGA_D];
__device__ float g_trans_part[3 * (size_t)KCOLS * TRANZ_D];

// ---------------------------------------------------------------------------
// PTX helpers (base ISA: ldmatrix / mma.sync / cp.async)
// ---------------------------------------------------------------------------
__device__ __forceinline__ uint32_t smem_u32(const void* p) {
    uint32_t a;
    asm("{ .reg .u64 t; cvta.to.shared.u64 t, %1; cvt.u32.u64 %0, t; }" : "=r"(a) : "l"(p));
    return a;
}
__device__ __forceinline__ void cp16(uint32_t s, const void* g) {
    asm volatile("cp.async.cg.shared.global [%0], [%1], 16;" :: "r"(s), "l"(g) : "memory");
}
#define CP_COMMIT() asm volatile("cp.async.commit_group;" ::: "memory")

__device__ __forceinline__ void ldsm_x4(uint32_t addr, uint32_t* r) {
    asm volatile("ldmatrix.sync.aligned.m8n8.x4.shared.b16 {%0,%1,%2,%3}, [%4];"
                 : "=r"(r[0]), "=r"(r[1]), "=r"(r[2]), "=r"(r[3]) : "r"(addr));
}
__device__ __forceinline__ void mma_f16(float* c, const uint32_t* a,
                                        uint32_t b0, uint32_t b1) {
    asm volatile(
        "mma.sync.aligned.m16n8k16.row.col.f32.f16.f16.f32 "
        "{%0,%1,%2,%3}, {%4,%5,%6,%7}, {%8,%9}, {%0,%1,%2,%3};"
        : "+f"(c[0]), "+f"(c[1]), "+f"(c[2]), "+f"(c[3])
        : "r"(a[0]), "r"(a[1]), "r"(a[2]), "r"(a[3]), "r"(b0), "r"(b1));
}

// ---------------------------------------------------------------------------
// Fused weight split: all 8 weights -> (hi, lo) fp16, one launch.
// ---------------------------------------------------------------------------
__global__ __launch_bounds__(256) void split_w_kernel(
    const float* __restrict__ w0, const float* __restrict__ w1,
    const float* __restrict__ w2, const float* __restrict__ w3,
    const float* __restrict__ w4, const float* __restrict__ w5,
    const float* __restrict__ w6, const float* __restrict__ w7,
    __half* __restrict__ hi, __half* __restrict__ lo)
{
    const int cum[8] = {65536, 1114112, 2162688, 2752512,
                        2818048, 3866624, 4915200, 5111808};
    int idx = blockIdx.x * 256 + threadIdx.x;
    if (idx >= 5111808) return;
    const float* srcs[8] = {w0, w1, w2, w3, w4, w5, w6, w7};
    int s = 0;
#pragma unroll
    for (int i = 0; i < 7; i++) s += (idx >= cum[i]);
    int local = idx - (s ? cum[s - 1] : 0);
    float4 v = ((const float4*)srcs[s])[local];
    float f[4] = {v.x, v.y, v.z, v.w};
    __align__(8) __half h[4], l[4];
#pragma unroll
    for (int j = 0; j < 4; j++) {
        h[j] = __float2half(f[j]);
        l[j] = __float2half(f[j] - __half2float(h[j]));
    }
    ((uint2*)hi)[idx] = *(const uint2*)h;
    ((uint2*)lo)[idx] = *(const uint2*)l;
}

// x (LATENT, KCOLS) -> xt (KCOLS, LATENT), plain fp16
__global__ __launch_bounds__(256) void split_xT_kernel(
    const float* __restrict__ x, __half* __restrict__ out)
{
    int i = blockIdx.x * 256 + threadIdx.x;  // i = n*LATENT + f
    int f = i & (LATENT - 1);
    int n = i >> 7;
    out[i] = __float2half(x[(size_t)f * KCOLS + n]);
}

// ---------------------------------------------------------------------------
// HMMA 2-MMA split GEMM:  C = (Ah + Al) @ B^T,  A = weights hi/lo fp16,
// B = activations plain fp16 (transposed layout, K-contiguous).
// Output TRANSPOSED [n][M]. mode 0: relu + fp16; mode 1: fp32 raw.
// CTA 128x128x32, 256 threads, warp tile 64x32, 3-stage cp.async, 2 CTAs/SM.
// ---------------------------------------------------------------------------
#define BM 128
#define BN 128
#define BK 32
#define GT 256
#define PITCH 80
#define TILE_B (128 * PITCH)      // 10240
#define OFF_AH 0
#define OFF_AL TILE_B
#define OFF_B  (2 * TILE_B)
#define STAGE_B (3 * TILE_B)      // 30720
#define NSTAGE 3
#define GEMM_SMEM (NSTAGE * STAGE_B)   // 92160

__device__ __forceinline__ void load_stage(
    const __half* __restrict__ Ah, const __half* __restrict__ Al,
    const __half* __restrict__ B, int Kd, int m0, int n0, int kk,
    uint32_t stage_sb, int tid)
{
    // 384 rows (Ah 128, Al 128, B 128), 4 x 16B chunks each = 1536 chunks.
#pragma unroll
    for (int i = 0; i < 6; i++) {
        const int c = tid + i * 256;
        const int row = c >> 2;
        const int cb = (c & 3) * 16;
        const __half* gsrc;
        int grow;
        uint32_t soff;
        if (row < 128)      { gsrc = Ah; grow = m0 + row;       soff = OFF_AH + row * PITCH; }
        else if (row < 256) { gsrc = Al; grow = m0 + row - 128; soff = OFF_AL + (row - 128) * PITCH; }
        else                { gsrc = B;  grow = n0 + row - 256; soff = OFF_B  + (row - 256) * PITCH; }
        cp16(stage_sb + soff + cb,
             (const char*)(gsrc + (size_t)grow * Kd + kk) + cb);
    }
}

__global__ __launch_bounds__(GT, 2) void gemm_hmma_kernel(
    const __half* __restrict__ A_hi, const __half* __restrict__ A_lo,
    const __half* __restrict__ B, __half* __restrict__ out_h,
    float* __restrict__ out_f32, int M, int Kd, int mode,
    int ktps, size_t out_stride)
{
    extern __shared__ __align__(128) char smem[];
    const uint32_t sb = smem_u32(smem);
    const int tid = threadIdx.x;
    const int lane = tid & 31;
    const int wid = tid >> 5;                 // 0..7
    const int warp_m0 = (wid & 1) * 64;
    const int warp_n0 = (wid >> 1) * 32;
    const int m0 = blockIdx.y * BM;
    const int n0 = blockIdx.x * BN;
    const int KT = Kd / BK;
    const int ktb = blockIdx.z * ktps;
    const int L = min(KT - ktb, ktps);
    out_f32 += (size_t)blockIdx.z * out_stride;

    const int a_row = (lane & 7) + ((lane >> 3) & 1) * 8;
    const int a_kb  = (lane >> 4) * 16;
    const int b_row = (lane & 7) + (lane >> 4) * 8;
    const int b_kb  = ((lane >> 3) & 1) * 16;

    float acc[4][4][4];
#pragma unroll
    for (int mt = 0; mt < 4; mt++)
#pragma unroll
        for (int nt = 0; nt < 4; nt++)
#pragma unroll
            for (int i = 0; i < 4; i++) acc[mt][nt][i] = 0.0f;

    load_stage(A_hi, A_lo, B, Kd, m0, n0, ktb * BK, sb, tid);
    CP_COMMIT();
    load_stage(A_hi, A_lo, B, Kd, m0, n0, (ktb + 1) * BK, sb + STAGE_B, tid);
    CP_COMMIT();

    for (int kt = 0; kt < L; kt++) {
        asm volatile("cp.async.wait_group 1;" ::: "memory");
        __syncthreads();

        if (kt + 2 < L) {
            load_stage(A_hi, A_lo, B, Kd, m0, n0, (ktb + kt + 2) * BK,
                       sb + ((kt + 2) % NSTAGE) * STAGE_B, tid);
        }
        CP_COMMIT();

        const uint32_t st = sb + (kt % NSTAGE) * STAGE_B;
#pragma unroll
        for (int ks = 0; ks < 2; ks++) {
            const int kb = ks * 32;
            uint32_t bq[2][4];
#pragma unroll
            for (int g = 0; g < 2; g++) {
                uint32_t rb = st + OFF_B + (warp_n0 + g * 16 + b_row) * PITCH + kb + b_kb;
                ldsm_x4(rb, bq[g]);
            }
#pragma unroll
            for (int mt = 0; mt < 4; mt++) {
                uint32_t ah[4], al[4];
                uint32_t ra = st + (warp_m0 + mt * 16 + a_row) * PITCH + kb + a_kb;
                ldsm_x4(ra + OFF_AH, ah);
                ldsm_x4(ra + OFF_AL, al);
#pragma unroll
                for (int nt = 0; nt < 4; nt++) {
                    const int g = nt >> 1, p = (nt & 1) * 2;
                    mma_f16(acc[mt][nt], ah, bq[g][p], bq[g][p + 1]);
                    mma_f16(acc[mt][nt], al, bq[g][p], bq[g][p + 1]);
                }
            }
        }
    }

    // ---------------- epilogue: transpose via SMEM (128 x 132 fp32) --------
    __syncthreads();
    float* sC = (float*)smem;
    const int crow = lane >> 2, ccol = (lane & 3) * 2;
#pragma unroll
    for (int mt = 0; mt < 4; mt++)
#pragma unroll
        for (int nt = 0; nt < 4; nt++) {
            const int m_ = warp_m0 + mt * 16 + crow;
            const int n_ = warp_n0 + nt * 8 + ccol;
            const float* c = acc[mt][nt];
            sC[(size_t)n_ * 132 + m_]           = c[0];
            sC[(size_t)(n_ + 1) * 132 + m_]     = c[1];
            sC[(size_t)n_ * 132 + m_ + 8]       = c[2];
            sC[(size_t)(n_ + 1) * 132 + m_ + 8] = c[3];
        }
    __syncthreads();

    const int r  = tid >> 1;          // n row 0..127
    const int mh = (tid & 1) * 64;    // m half
    const size_t base = (size_t)(n0 + r) * M + m0 + mh;
    const float* srow = &sC[(size_t)r * 132 + mh];
    if (mode == 0) {
#pragma unroll
        for (int j0 = 0; j0 < 64; j0 += 8) {
            __align__(16) __half h8[8];
#pragma unroll
            for (int j = 0; j < 8; j++)
                h8[j] = __float2half(fmaxf(srow[j0 + j], 0.0f));
            *(uint4*)(out_h + base + j0) = *(const uint4*)h8;
        }
    } else {
#pragma unroll
        for (int j0 = 0; j0 < 64; j0 += 4) {
            float4 v;
            v.x = srow[j0 + 0]; v.y = srow[j0 + 1];
            v.z = srow[j0 + 2]; v.w = srow[j0 + 3];
            *(float4*)(out_f32 + base + j0) = v;
        }
    }
}

// ---------------------------------------------------------------------------
// expm (3x3) + output assembly; sums split-K partials (2 omega, 3 trans).
// ---------------------------------------------------------------------------
__device__ __forceinline__ void mm3(const float* X, const float* Y, float* Z) {
#pragma unroll
    for (int r = 0; r < 3; r++)
#pragma unroll
        for (int c = 0; c < 3; c++)
            Z[3 * r + c] = fmaf(X[3 * r + 0], Y[c],
                           fmaf(X[3 * r + 1], Y[3 + c], X[3 * r + 2] * Y[6 + c]));
}

__device__ void expm3(const float* A, float* E) {
    float n0 = fabsf(A[0]) + fabsf(A[1]) + fabsf(A[2]);
    float n1 = fabsf(A[3]) + fabsf(A[4]) + fabsf(A[5]);
    float n2 = fabsf(A[6]) + fabsf(A[7]) + fabsf(A[8]);
    float nrm = fmaxf(n0, fmaxf(n1, n2));
    int s = 0;
    if (nrm > 0.25f) {
        s = (int)ceilf(log2f(nrm * 4.0f));
        if (s < 0) s = 0;
    }
    float sc = exp2f((float)(-s));
    float B[9], T[9];
#pragma unroll
    for (int i = 0; i < 9; i++) B[i] = A[i] * sc;
#pragma unroll
    for (int i = 0; i < 9; i++) {
        T[i] = B[i];
        E[i] = ((i == 0) | (i == 4) | (i == 8)) ? 1.0f + B[i] : B[i];
    }
#pragma unroll
    for (int j = 2; j <= 10; j++) {
        float Tn[9];
        mm3(T, B, Tn);
        float inv = 1.0f / (float)j;
#pragma unroll
        for (int i = 0; i < 9; i++) { Tn[i] *= inv; E[i] += Tn[i]; T[i] = Tn[i]; }
    }
    for (int q = 0; q < s; q++) {
        float S[9];
        mm3(E, E, S);
#pragma unroll
        for (int i = 0; i < 9; i++) E[i] = S[i];
    }
}

__global__ __launch_bounds__(256) void expm_assemble_kernel(
    const float* __restrict__ omega_part, // 2 x (K, 9n)
    const float* __restrict__ trans_part, // 3 x (K, 3n)
    float* __restrict__ omega_out,        // (9n, K)
    float* __restrict__ transf,           // (12n, K)
    float* __restrict__ rot,              // (9n, K)
    float* __restrict__ trans_out)        // (3n, K)
{
    const int n = blockIdx.x * 256 + threadIdx.x;
    const int p = blockIdx.y;
    const size_t SO = (size_t)KCOLS * OMEGA_D;
    const size_t ST = (size_t)KCOLS * TRANZ_D;

    float Am[9];
    const size_t obase = (size_t)n * OMEGA_D + 9 * p;
#pragma unroll
    for (int j = 0; j < 9; j++)
        Am[j] = __ldg(omega_part + obase + j) + __ldg(omega_part + SO + obase + j);

    float E[9];
    expm3(Am, E);

#pragma unroll
    for (int j = 0; j < 9; j++) {
        omega_out[(size_t)(9 * p + j) * KCOLS + n] = Am[j];
        rot[(size_t)(9 * p + j) * KCOLS + n]       = E[j];
        transf[(size_t)(12 * p + j) * KCOLS + n]   = E[j];
    }
    const size_t tbase = (size_t)n * TRANZ_D + 3 * p;
#pragma unroll
    for (int c = 0; c < 3; c++) {
        float tv = __ldg(trans_part + tbase + c)
                 + __ldg(trans_part + ST + tbase + c)
                 + __ldg(trans_part + 2 * ST + tbase + c);
        trans_out[(size_t)(3 * p + c) * KCOLS + n]   = tv;
        transf[(size_t)(12 * p + 9 + c) * KCOLS + n] = tv;
    }
}

// ---------------------------------------------------------------------------
// kernel_launch
// ---------------------------------------------------------------------------
extern "C" void kernel_launch(void* const* d_in, const int* in_sizes, int n_in,
                              void* d_out, int out_size)
{
    const float* x = (const float*)d_in[0];
    const float* W[8];
    for (int i = 0; i < 8; i++) W[i] = (const float*)d_in[1 + i];

    const int wsz[8] = {2048 * 128, 2048 * 2048, 2048 * 2048, 1152 * 2048,
                        2048 * 128, 2048 * 2048, 2048 * 2048, 384 * 2048};
    size_t woff[8];
    size_t acc = 0;
    for (int i = 0; i < 8; i++) { woff[i] = acc; acc += wsz[i]; }

    float* out    = (float*)d_out;
    float* omega  = out;
    float* transf = omega  + (size_t)OMEGA_D  * KCOLS;
    float* rot    = transf + (size_t)TRANSF_D * KCOLS;
    float* trans  = rot    + (size_t)OMEGA_D  * KCOLS;

    __half *w_hi, *w_lo, *xt, *a0, *a1;
    float *omega_part, *trans_part;
    cudaGetSymbolAddress((void**)&w_hi, g_w_hi);
    cudaGetSymbolAddress((void**)&w_lo, g_w_lo);
    cudaGetSymbolAddress((void**)&xt, g_xt);
    {
        __half* p;
        cudaGetSymbolAddress((void**)&p, g_act);
        a0 = p; a1 = p + (size_t)HIDDEN * KCOLS;
    }
    cudaGetSymbolAddress((void**)&omega_part, g_omega_part);
    cudaGetSymbolAddress((void**)&trans_part, g_trans_part);

    cudaFuncSetAttribute(gemm_hmma_kernel,
                         cudaFuncAttributeMaxDynamicSharedMemorySize, GEMM_SMEM);

    // 1) fused weight split + xT convert
    split_w_kernel<<<(5111808 + 255) / 256, 256>>>(
        W[0], W[1], W[2], W[3], W[4], W[5], W[6], W[7], w_hi, w_lo);
    split_xT_kernel<<<(KCOLS * LATENT) / 256, 256>>>(x, xt);

    // 2) GEMM chains
    auto gemm = [&](int wi, const __half* b, __half* oh, float* of,
                    int M, int Kd, int mode, int zsplits, size_t ostride) {
        int KT = Kd / BK;
        int ktps = (KT + zsplits - 1) / zsplits;
        dim3 grid(KCOLS / BN, M / BM, zsplits);
        gemm_hmma_kernel<<<grid, GT, GEMM_SMEM>>>(
            w_hi + woff[wi], w_lo + woff[wi], b, oh, of,
            M, Kd, mode, ktps, ostride);
    };

    // omega branch (layer3 split-K x2)
    gemm(0, xt, a0, nullptr, HIDDEN,  LATENT, 0, 1, 0);
    gemm(1, a0, a1, nullptr, HIDDEN,  HIDDEN, 0, 1, 0);
    gemm(2, a1, a0, nullptr, HIDDEN,  HIDDEN, 0, 1, 0);
    gemm(3, a0, nullptr, omega_part, OMEGA_D, HIDDEN, 1, 2,
         (size_t)KCOLS * OMEGA_D);
    // translation branch (layer7 split-K x3)
    gemm(4, xt, a0, nullptr, HIDDEN,  LATENT, 0, 1, 0);
    gemm(5, a0, a1, nullptr, HIDDEN,  HIDDEN, 0, 1, 0);
    gemm(6, a1, a0, nullptr, HIDDEN,  HIDDEN, 0, 1, 0);
    gemm(7, a0, nullptr, trans_part, TRANZ_D, HIDDEN, 1, 3,
         (size_t)KCOLS * TRANZ_D);

    // 3) expm + assembly
    dim3 ge(KCOLS / 256, NPARTS);
    expm_assemble_kernel<<<ge, 256>>>(omega_part, trans_part, omega, transf,
                                      rot, trans);
}